// round 9
// baseline (speedup 1.0000x reference)
#include <cuda_runtime.h>
#include <math.h>

#define BATCH 8
#define HF    128
#define PIX   (HF*HF)
#define NOG   384
#define NIMP  96
#define NPTS  128
#define INC   512
#define HID2  256
#define KFEAT 514
#define KFP   528
#define COUT  2
#define NROWS (BATCH*NPTS) // 1024
#define SQRT1_2 0.70710678118654752440f

// ---------------- scratch ----------------
__device__ float g_points[BATCH*NPTS*2];
__device__ float g_feat  [NROWS*KFP];
__device__ float g_t1    [NROWS*INC];

// ---------------- bilinear helper ----------------
struct Bilin { int l00,l10,l01,l11; float w00,w10,w01,w11; };

__device__ __forceinline__ Bilin make_bilin(float px, float py) {
    Bilin r;
    float gx = ((2.0f*px - 1.0f + 1.0f)*(float)HF - 1.0f)*0.5f;
    float gy = ((2.0f*py - 1.0f + 1.0f)*(float)HF - 1.0f)*0.5f;
    float x0f = floorf(gx), y0f = floorf(gy);
    float wx1 = gx - x0f,  wy1 = gy - y0f;
    float wx0 = 1.0f - wx1, wy0 = 1.0f - wy1;
    int x0 = (int)x0f, y0 = (int)y0f;
    int x1 = x0 + 1,   y1 = y0 + 1;
    bool vx0 = (x0 >= 0) && (x0 <= HF-1);
    bool vx1 = (x1 >= 0) && (x1 <= HF-1);
    bool vy0 = (y0 >= 0) && (y0 <= HF-1);
    bool vy1 = (y1 >= 0) && (y1 <= HF-1);
    int x0c = min(max(x0,0),HF-1), x1c = min(max(x1,0),HF-1);
    int y0c = min(max(y0,0),HF-1), y1c = min(max(y1,0),HF-1);
    r.l00 = y0c*HF + x0c;  r.l10 = y0c*HF + x1c;
    r.l01 = y1c*HF + x0c;  r.l11 = y1c*HF + x1c;
    r.w00 = (vx0 && vy0) ? wx0*wy0 : 0.0f;
    r.w10 = (vx1 && vy0) ? wx1*wy0 : 0.0f;
    r.w01 = (vx0 && vy1) ? wx0*wy1 : 0.0f;
    r.w11 = (vx1 && vy1) ? wx1*wy1 : 0.0f;
    return r;
}

// ---------------- K1: sampling points ----------------
__global__ void __launch_bounds__(NOG) k_points(
    const float* __restrict__ out, const float* __restrict__ over_gen,
    const float* __restrict__ rand_point, float* __restrict__ pts_out)
{
    int b = blockIdx.x, tid = threadIdx.x;
    __shared__ float s_unc[NOG];
    const float* ob = out + (size_t)b*2*PIX;

    float px = over_gen[((size_t)b*NOG + tid)*2 + 0];
    float py = over_gen[((size_t)b*NOG + tid)*2 + 1];
    {
        Bilin bl = make_bilin(px, py);
        float a00 = ob[bl.l00], b00 = ob[PIX + bl.l00];
        float a10 = ob[bl.l10], b10 = ob[PIX + bl.l10];
        float a01 = ob[bl.l01], b01 = ob[PIX + bl.l01];
        float a11 = ob[bl.l11], b11 = ob[PIX + bl.l11];
        float og0 = bl.w00*fmaxf(a00,b00) + bl.w10*fmaxf(a10,b10)
                  + bl.w01*fmaxf(a01,b01) + bl.w11*fmaxf(a11,b11);
        float og1 = bl.w00*fminf(a00,b00) + bl.w10*fminf(a10,b10)
                  + bl.w01*fminf(a01,b01) + bl.w11*fminf(a11,b11);
        s_unc[tid] = og1 - og0;
    }
    __syncthreads();
    {
        float u = s_unc[tid];
        int rank = 0;
        #pragma unroll 8
        for (int j = 0; j < NOG; j++) {
            float uj = s_unc[j];
            rank += (uj > u) || (uj == u && j < tid);   // stable
        }
        if (rank < NIMP) {
            float2 p = make_float2(px, py);
            ((float2*)g_points)[b*NPTS + rank] = p;
            ((float2*)pts_out )[b*NPTS + rank] = p;
        }
    }
    if (tid < 16) {
        float2 z = make_float2(0.f, 0.f);
        ((float2*)g_points)[b*NPTS + NIMP + tid] = z;
        ((float2*)pts_out )[b*NPTS + NIMP + tid] = z;
        float2 rp = ((const float2*)rand_point)[b*16 + tid];
        ((float2*)g_points)[b*NPTS + NIMP + 16 + tid] = rp;
        ((float2*)pts_out )[b*NPTS + NIMP + 16 + tid] = rp;
    }
}

// ---------------- K2: gather feat rows ----------------
__global__ void __launch_bounds__(128) k_feat(
    const float* __restrict__ out, const float* __restrict__ res2)
{
    int idx = blockIdx.x;            // b*128 + n
    int b = idx >> 7;
    int tid = threadIdx.x;
    float2 p = ((const float2*)g_points)[idx];
    Bilin bl = make_bilin(p.x, p.y);
    const float* rb = res2 + (size_t)b*INC*PIX;
    float* frow = g_feat + (size_t)idx*KFP;

    #pragma unroll 4
    for (int c = tid; c < INC; c += 128) {
        const float* pp = rb + (size_t)c*PIX;
        frow[2 + c] = bl.w00*pp[bl.l00] + bl.w10*pp[bl.l10]
                    + bl.w01*pp[bl.l01] + bl.w11*pp[bl.l11];
    }
    if (tid < 2) {
        const float* pp = out + (size_t)(b*2 + tid)*PIX;
        frow[tid] = bl.w00*pp[bl.l00] + bl.w10*pp[bl.l10]
                  + bl.w01*pp[bl.l01] + bl.w11*pp[bl.l11];
    }
    if (tid >= 2 && tid < 16) frow[512 + tid] = 0.0f;
}

// ---------------- GEMM1 + bias: packed f32x2 over N, double-buffered -------
#define FMA2(d,a,b) asm("fma.rn.f32x2 %0, %1, %2, %0;" \
                        : "+l"(d) : "l"(a), "l"(b))

template<int KREAL, int KP, int LDA, int N, int BM, int TM>
__global__ void __launch_bounds__(256) k_gemm(
    const float* __restrict__ A, const float* __restrict__ W,
    const float* __restrict__ bias, float* __restrict__ C)
{
    constexpr int BK = 16, BN = 64;
    constexpr int KT = KP / BK;
    __shared__ float sA[2][BK][BM + 4];
    __shared__ float sW[2][BK][BN];

    int tid = threadIdx.x;
    int tx = tid & 15, ty = tid >> 4;
    int row0 = blockIdx.y * BM, col0 = blockIdx.x * BN;

    int a_m = tid >> 2, a_k = (tid & 3) * 4;
    int w_k = tid >> 4, w_n = (tid & 15) * 4;
    const bool aload = (BM * 4 == 256) || (tid < BM * 4);

    float4 av = make_float4(0,0,0,0), wv;
    if (aload) av = *(const float4*)&A[(size_t)(row0 + a_m)*LDA + a_k];
    wv = (w_k < KREAL) ? *(const float4*)&W[(size_t)w_k*N + col0 + w_n]
                       : make_float4(0,0,0,0);
    if (aload) {
        sA[0][a_k+0][a_m] = av.x; sA[0][a_k+1][a_m] = av.y;
        sA[0][a_k+2][a_m] = av.z; sA[0][a_k+3][a_m] = av.w;
    }
    *(float4*)&sW[0][w_k][w_n] = wv;
    __syncthreads();

    unsigned long long acc2[TM][2];
    #pragma unroll
    for (int i = 0; i < TM; i++) { acc2[i][0] = 0ull; acc2[i][1] = 0ull; }

    for (int t = 0; t < KT; t++) {
        int buf = t & 1;
        if (t + 1 < KT) {
            int k0 = (t + 1) * BK;
            if (aload) av = *(const float4*)&A[(size_t)(row0 + a_m)*LDA + k0 + a_k];
            int kg = k0 + w_k;
            wv = (kg < KREAL) ? *(const float4*)&W[(size_t)kg*N + col0 + w_n]
                              : make_float4(0,0,0,0);
        }
        #pragma unroll
        for (int kk = 0; kk < BK; kk++) {
            float a[TM];
            if (TM == 4) {
                float4 v = *(const float4*)&sA[buf][kk][ty*4];
                a[0]=v.x; a[1]=v.y; a[2]=v.z; a[3]=v.w;
            } else {
                float2 v = *(const float2*)&sA[buf][kk][ty*2];
                a[0]=v.x; a[1]=v.y;
            }
            ulonglong2 wp = *(const ulonglong2*)&sW[buf][kk][tx*4];
            #pragma unroll
            for (int i = 0; i < TM; i++) {
                unsigned long long ad;
                asm("mov.b64 %0, {%1, %1};" : "=l"(ad) : "f"(a[i]));
                FMA2(acc2[i][0], ad, wp.x);
                FMA2(acc2[i][1], ad, wp.y);
            }
        }
        if (t + 1 < KT) {
            int nb = buf ^ 1;
            if (aload) {
                sA[nb][a_k+0][a_m] = av.x; sA[nb][a_k+1][a_m] = av.y;
                sA[nb][a_k+2][a_m] = av.z; sA[nb][a_k+3][a_m] = av.w;
            }
            *(float4*)&sW[nb][w_k][w_n] = wv;
            __syncthreads();
        }
    }

    float4 bv = *(const float4*)&bias[col0 + tx*4];
    #pragma unroll
    for (int i = 0; i < TM; i++) {
        float c0, c1, c2, c3;
        asm("mov.b64 {%0, %1}, %2;" : "=f"(c0), "=f"(c1) : "l"(acc2[i][0]));
        asm("mov.b64 {%0, %1}, %2;" : "=f"(c2), "=f"(c3) : "l"(acc2[i][1]));
        float4 v = make_float4(c0 + bv.x, c1 + bv.y, c2 + bv.z, c3 + bv.w);
        *(float4*)&C[(size_t)(row0 + ty*TM + i)*N + col0 + tx*4] = v;
    }
}

__device__ __forceinline__ float gelu_exact(float z) {
    return 0.5f * z * (1.0f + erff(z * SQRT1_2));
}

// ---------------- MEGA v3: LN1+GELU -> GEMM(W2)+b2 -> LN2+GELU -> w3 -------
// 128 blocks x 256 threads. Thread owns 1 column (tid) x 8 rows.
// W2 column read DIRECTLY from global (coalesced per warp, L2-resident);
// NO smem staging of W, NO barriers in the main loop -> deep LDG pipelining.
__global__ void __launch_bounds__(256) k_mega(
    const float* __restrict__ gt1,
    const float* __restrict__ g1v, const float* __restrict__ be1,
    const float* __restrict__ w2,  const float* __restrict__ b2,
    const float* __restrict__ g2v, const float* __restrict__ be2,
    const float* __restrict__ w3,  const float* __restrict__ b3,
    const float* __restrict__ mask, float* __restrict__ rend)
{
    __shared__ float sA[8][INC];                 // 16 KB (post LN1+GELU)

    int tid = threadIdx.x, warp = tid >> 5, lane = tid & 31;
    int row0 = blockIdx.x * 8;
    int row = row0 + warp;

    // ---- LN1 + GELU (warp-private: each warp its own row) ----
    {
        const float4* xr = (const float4*)(gt1 + (size_t)row*INC);
        float4 v[4]; float s = 0.0f;
        #pragma unroll
        for (int i = 0; i < 4; i++) {
            v[i] = xr[lane + 32*i];
            s += v[i].x + v[i].y + v[i].z + v[i].w;
        }
        #pragma unroll
        for (int o = 16; o; o >>= 1) s += __shfl_xor_sync(0xffffffff, s, o);
        float m = s * (1.0f/INC);
        float var = 0.0f;
        #pragma unroll
        for (int i = 0; i < 4; i++) {
            float dx=v[i].x-m, dy=v[i].y-m, dz=v[i].z-m, dw=v[i].w-m;
            var += dx*dx + dy*dy + dz*dz + dw*dw;
        }
        #pragma unroll
        for (int o = 16; o; o >>= 1) var += __shfl_xor_sync(0xffffffff, var, o);
        float inv = rsqrtf(var * (1.0f/INC) + 1e-5f);
        #pragma unroll
        for (int i = 0; i < 4; i++) {
            int c4 = lane + 32*i;
            float4 gg = ((const float4*)g1v)[c4];
            float4 ee = ((const float4*)be1)[c4];
            float4 o4;
            o4.x = gelu_exact((v[i].x - m)*inv*gg.x + ee.x);
            o4.y = gelu_exact((v[i].y - m)*inv*gg.y + ee.y);
            o4.z = gelu_exact((v[i].z - m)*inv*gg.z + ee.z);
            o4.w = gelu_exact((v[i].w - m)*inv*gg.w + ee.w);
            ((float4*)sA[warp])[c4] = o4;
        }
    }
    __syncthreads();   // sA complete

    // ---- GEMM: direct-LDG W column, barrier-free, k-pair packed ----
    unsigned long long acc2[8];
    #pragma unroll
    for (int r = 0; r < 8; r++) acc2[r] = 0ull;

    const float* wcol = w2 + tid;   // this thread's W2 column
    #pragma unroll 4
    for (int k4 = 0; k4 < INC; k4 += 4) {
        float w0 = __ldg(&wcol[(size_t)(k4+0)*HID2]);
        float w1 = __ldg(&wcol[(size_t)(k4+1)*HID2]);
        float w2s= __ldg(&wcol[(size_t)(k4+2)*HID2]);
        float w3s= __ldg(&wcol[(size_t)(k4+3)*HID2]);
        unsigned long long wd0, wd1;
        asm("mov.b64 %0, {%1, %2};" : "=l"(wd0) : "f"(w0), "f"(w1));
        asm("mov.b64 %0, {%1, %2};" : "=l"(wd1) : "f"(w2s), "f"(w3s));
        #pragma unroll
        for (int r = 0; r < 8; r++) {
            ulonglong2 ap = *(const ulonglong2*)&sA[r][k4];   // broadcast LDS
            FMA2(acc2[r], ap.x, wd0);
            FMA2(acc2[r], ap.y, wd1);
        }
    }

    // ---- unpack + bias ----
    float c[8];
    float b2v = b2[tid];
    #pragma unroll
    for (int r = 0; r < 8; r++) {
        float lo, hi;
        asm("mov.b64 {%0, %1}, %2;" : "=f"(lo), "=f"(hi) : "l"(acc2[r]));
        c[r] = lo + hi + b2v;
    }

    // ---- stage through smem (reuse sA): sOut[r][col] ----
    float* sOut = &sA[0][0];
    __syncthreads();   // all GEMM reads of sA complete
    #pragma unroll
    for (int r = 0; r < 8; r++) sOut[r*HID2 + tid] = c[r];
    __syncthreads();

    // ---- warp w: LN2 + GELU + w3 projection for row (row0 + w) ----
    float cc[8];
    {
        float4 cA = *(const float4*)&sOut[warp*HID2 + lane*8];
        float4 cB = *(const float4*)&sOut[warp*HID2 + lane*8 + 4];
        cc[0]=cA.x; cc[1]=cA.y; cc[2]=cA.z; cc[3]=cA.w;
        cc[4]=cB.x; cc[5]=cB.y; cc[6]=cB.z; cc[7]=cB.w;
    }
    float s2 = 0.0f;
    #pragma unroll
    for (int j = 0; j < 8; j++) s2 += cc[j];
    #pragma unroll
    for (int o = 16; o; o >>= 1) s2 += __shfl_xor_sync(0xffffffff, s2, o);
    float m2 = s2 * (1.0f/HID2);
    float v2 = 0.0f;
    #pragma unroll
    for (int j = 0; j < 8; j++) { float d = cc[j]-m2; v2 += d*d; }
    #pragma unroll
    for (int o = 16; o; o >>= 1) v2 += __shfl_xor_sync(0xffffffff, v2, o);
    float inv2 = rsqrtf(v2 * (1.0f/HID2) + 1e-5f);

    float h[8];
    {
        float4 gA = ((const float4*)g2v)[lane*2], gB = ((const float4*)g2v)[lane*2+1];
        float4 eA = ((const float4*)be2)[lane*2], eB = ((const float4*)be2)[lane*2+1];
        float gs[8] = {gA.x,gA.y,gA.z,gA.w,gB.x,gB.y,gB.z,gB.w};
        float es[8] = {eA.x,eA.y,eA.z,eA.w,eB.x,eB.y,eB.z,eB.w};
        #pragma unroll
        for (int j = 0; j < 8; j++)
            h[j] = gelu_exact((cc[j]-m2)*inv2*gs[j] + es[j]);
    }
    float a0 = 0.0f, a1 = 0.0f;
    #pragma unroll
    for (int j = 0; j < 4; j++) {
        float4 w = ((const float4*)w3)[lane*4 + j];   // rows lane*8+2j, +2j+1
        a0 += h[2*j]*w.x + h[2*j+1]*w.z;
        a1 += h[2*j]*w.y + h[2*j+1]*w.w;
    }
    #pragma unroll
    for (int o = 16; o; o >>= 1) {
        a0 += __shfl_xor_sync(0xffffffff, a0, o);
        a1 += __shfl_xor_sync(0xffffffff, a1, o);
    }
    if (lane == 0) {
        int b = row >> 7, n = row & 127;
        float c0 = g_feat[(size_t)row*KFP + 0];
        float c1 = g_feat[(size_t)row*KFP + 1];
        float m0 = mask[(size_t)(b*COUT + 0)*NPTS + n];
        float m1 = mask[(size_t)(b*COUT + 1)*NPTS + n];
        rend[(size_t)(b*COUT + 0)*NPTS + n] = (a0 + b3[0])*m0 + c0;
        rend[(size_t)(b*COUT + 1)*NPTS + n] = (a1 + b3[1])*m1 + c1;
    }
}

// ---------------- launch ----------------
extern "C" void kernel_launch(void* const* d_in, const int* in_sizes, int n_in,
                              void* d_out, int out_size)
{
    const float* res2       = (const float*)d_in[1];
    const float* out        = (const float*)d_in[2];
    const float* over_gen   = (const float*)d_in[3];
    const float* rand_point = (const float*)d_in[4];
    const float* mask       = (const float*)d_in[5];
    const float* w1  = (const float*)d_in[6];
    const float* b1  = (const float*)d_in[7];
    const float* g1  = (const float*)d_in[8];
    const float* be1 = (const float*)d_in[9];
    const float* w2  = (const float*)d_in[10];
    const float* b2  = (const float*)d_in[11];
    const float* g2  = (const float*)d_in[12];
    const float* be2 = (const float*)d_in[13];
    const float* w3  = (const float*)d_in[14];
    const float* b3  = (const float*)d_in[15];

    float* o_rend = (float*)d_out;                      // [8,2,128]
    float* o_pts  = o_rend + (size_t)BATCH*COUT*NPTS;   // [8,128,2]

    float* gf;  cudaGetSymbolAddress((void**)&gf,  g_feat);
    float* gt1; cudaGetSymbolAddress((void**)&gt1, g_t1);

    k_points<<<BATCH, NOG>>>(out, over_gen, rand_point, o_pts);
    k_feat  <<<BATCH*NPTS, 128>>>(out, res2);

    dim3 g1g(INC/64, NROWS/64);
    k_gemm<KFEAT, KFP, KFP, INC, 64, 4><<<g1g, 256>>>(gf, w1, b1, gt1);

    k_mega<<<NROWS/8, 256>>>(gt1, g1, be1, w2, b2, g2, be2, w3, b3, mask, o_rend);
}

// round 12
// speedup vs baseline: 1.0827x; 1.0827x over previous
#include <cuda_runtime.h>
#include <math.h>

#define BATCH 8
#define HF    128
#define PIX   (HF*HF)
#define NOG   384
#define NIMP  96
#define NPTS  128
#define INC   512
#define HID2  256
#define KFEAT 514
#define KFP   528
#define COUT  2
#define NROWS (BATCH*NPTS) // 1024
#define SQRT1_2 0.70710678118654752440f

// ---------------- scratch ----------------
__device__ float g_points[BATCH*NPTS*2];
__device__ float g_feat  [NROWS*KFP];
__device__ float g_t1    [NROWS*INC];

// ---------------- bilinear helper ----------------
struct Bilin { int l00,l10,l01,l11; float w00,w10,w01,w11; };

__device__ __forceinline__ Bilin make_bilin(float px, float py) {
    Bilin r;
    float gx = ((2.0f*px - 1.0f + 1.0f)*(float)HF - 1.0f)*0.5f;
    float gy = ((2.0f*py - 1.0f + 1.0f)*(float)HF - 1.0f)*0.5f;
    float x0f = floorf(gx), y0f = floorf(gy);
    float wx1 = gx - x0f,  wy1 = gy - y0f;
    float wx0 = 1.0f - wx1, wy0 = 1.0f - wy1;
    int x0 = (int)x0f, y0 = (int)y0f;
    int x1 = x0 + 1,   y1 = y0 + 1;
    bool vx0 = (x0 >= 0) && (x0 <= HF-1);
    bool vx1 = (x1 >= 0) && (x1 <= HF-1);
    bool vy0 = (y0 >= 0) && (y0 <= HF-1);
    bool vy1 = (y1 >= 0) && (y1 <= HF-1);
    int x0c = min(max(x0,0),HF-1), x1c = min(max(x1,0),HF-1);
    int y0c = min(max(y0,0),HF-1), y1c = min(max(y1,0),HF-1);
    r.l00 = y0c*HF + x0c;  r.l10 = y0c*HF + x1c;
    r.l01 = y1c*HF + x0c;  r.l11 = y1c*HF + x1c;
    r.w00 = (vx0 && vy0) ? wx0*wy0 : 0.0f;
    r.w10 = (vx1 && vy0) ? wx1*wy0 : 0.0f;
    r.w01 = (vx0 && vy1) ? wx0*wy1 : 0.0f;
    r.w11 = (vx1 && vy1) ? wx1*wy1 : 0.0f;
    return r;
}

// ---------------- K1: sampling points ----------------
__global__ void __launch_bounds__(NOG) k_points(
    const float* __restrict__ out, const float* __restrict__ over_gen,
    const float* __restrict__ rand_point, float* __restrict__ pts_out)
{
    int b = blockIdx.x, tid = threadIdx.x;
    __shared__ float s_unc[NOG];
    const float* ob = out + (size_t)b*2*PIX;

    float px = over_gen[((size_t)b*NOG + tid)*2 + 0];
    float py = over_gen[((size_t)b*NOG + tid)*2 + 1];
    {
        Bilin bl = make_bilin(px, py);
        float a00 = ob[bl.l00], b00 = ob[PIX + bl.l00];
        float a10 = ob[bl.l10], b10 = ob[PIX + bl.l10];
        float a01 = ob[bl.l01], b01 = ob[PIX + bl.l01];
        float a11 = ob[bl.l11], b11 = ob[PIX + bl.l11];
        float og0 = bl.w00*fmaxf(a00,b00) + bl.w10*fmaxf(a10,b10)
                  + bl.w01*fmaxf(a01,b01) + bl.w11*fmaxf(a11,b11);
        float og1 = bl.w00*fminf(a00,b00) + bl.w10*fminf(a10,b10)
                  + bl.w01*fminf(a01,b01) + bl.w11*fminf(a11,b11);
        s_unc[tid] = og1 - og0;
    }
    __syncthreads();
    {
        float u = s_unc[tid];
        int rank = 0;
        #pragma unroll 8
        for (int j = 0; j < NOG; j++) {
            float uj = s_unc[j];
            rank += (uj > u) || (uj == u && j < tid);   // stable
        }
        if (rank < NIMP) {
            float2 p = make_float2(px, py);
            ((float2*)g_points)[b*NPTS + rank] = p;
            ((float2*)pts_out )[b*NPTS + rank] = p;
        }
    }
    if (tid < 16) {
        float2 z = make_float2(0.f, 0.f);
        ((float2*)g_points)[b*NPTS + NIMP + tid] = z;
        ((float2*)pts_out )[b*NPTS + NIMP + tid] = z;
        float2 rp = ((const float2*)rand_point)[b*16 + tid];
        ((float2*)g_points)[b*NPTS + NIMP + 16 + tid] = rp;
        ((float2*)pts_out )[b*NPTS + NIMP + 16 + tid] = rp;
    }
}

// ---------------- K2: gather feat rows ----------------
__global__ void __launch_bounds__(128) k_feat(
    const float* __restrict__ out, const float* __restrict__ res2)
{
    int idx = blockIdx.x;            // b*128 + n
    int b = idx >> 7;
    int tid = threadIdx.x;
    float2 p = ((const float2*)g_points)[idx];
    Bilin bl = make_bilin(p.x, p.y);
    const float* rb = res2 + (size_t)b*INC*PIX;
    float* frow = g_feat + (size_t)idx*KFP;

    #pragma unroll 4
    for (int c = tid; c < INC; c += 128) {
        const float* pp = rb + (size_t)c*PIX;
        frow[2 + c] = bl.w00*pp[bl.l00] + bl.w10*pp[bl.l10]
                    + bl.w01*pp[bl.l01] + bl.w11*pp[bl.l11];
    }
    if (tid < 2) {
        const float* pp = out + (size_t)(b*2 + tid)*PIX;
        frow[tid] = bl.w00*pp[bl.l00] + bl.w10*pp[bl.l10]
                  + bl.w01*pp[bl.l01] + bl.w11*pp[bl.l11];
    }
    if (tid >= 2 && tid < 16) frow[512 + tid] = 0.0f;
}

// ---------------- packed f32x2 helpers ----------------
__device__ __forceinline__ void fma2(unsigned long long& d,
                                     unsigned long long a, unsigned long long b) {
    asm("fma.rn.f32x2 %0, %1, %2, %0;" : "+l"(d) : "l"(a), "l"(b));
}
__device__ __forceinline__ unsigned long long pack2(float lo, float hi) {
    unsigned long long d;
    asm("mov.b64 %0, {%1, %2};" : "=l"(d) : "f"(lo), "f"(hi));
    return d;
}
__device__ __forceinline__ unsigned long long bcast2(float a) {
    unsigned long long d;
    asm("mov.b64 %0, {%1, %1};" : "=l"(d) : "f"(a));
    return d;
}
__device__ __forceinline__ void unpack2(float& lo, float& hi, unsigned long long d) {
    asm("mov.b64 {%0, %1}, %2;" : "=f"(lo), "=f"(hi) : "l"(d));
}

// ---------------- GEMM1 + bias: packed f32x2 over N, double-buffered -------
template<int KREAL, int KP, int LDA, int N, int BM, int TM>
__global__ void __launch_bounds__(256) k_gemm(
    const float* __restrict__ A, const float* __restrict__ W,
    const float* __restrict__ bias, float* __restrict__ C)
{
    constexpr int BK = 16, BN = 64;
    constexpr int KT = KP / BK;
    __shared__ float sA[2][BK][BM + 4];
    __shared__ float sW[2][BK][BN];

    int tid = threadIdx.x;
    int tx = tid & 15, ty = tid >> 4;
    int row0 = blockIdx.y * BM, col0 = blockIdx.x * BN;

    int a_m = tid >> 2, a_k = (tid & 3) * 4;
    int w_k = tid >> 4, w_n = (tid & 15) * 4;
    const bool aload = (BM * 4 == 256) || (tid < BM * 4);

    float4 av = make_float4(0,0,0,0), wv;
    if (aload) av = *(const float4*)&A[(size_t)(row0 + a_m)*LDA + a_k];
    wv = (w_k < KREAL) ? *(const float4*)&W[(size_t)w_k*N + col0 + w_n]
                       : make_float4(0,0,0,0);
    if (aload) {
        sA[0][a_k+0][a_m] = av.x; sA[0][a_k+1][a_m] = av.y;
        sA[0][a_k+2][a_m] = av.z; sA[0][a_k+3][a_m] = av.w;
    }
    *(float4*)&sW[0][w_k][w_n] = wv;
    __syncthreads();

    unsigned long long acc2[TM][2];
    #pragma unroll
    for (int i = 0; i < TM; i++) { acc2[i][0] = 0ull; acc2[i][1] = 0ull; }

    for (int t = 0; t < KT; t++) {
        int buf = t & 1;
        if (t + 1 < KT) {
            int k0 = (t + 1) * BK;
            if (aload) av = *(const float4*)&A[(size_t)(row0 + a_m)*LDA + k0 + a_k];
            int kg = k0 + w_k;
            wv = (kg < KREAL) ? *(const float4*)&W[(size_t)kg*N + col0 + w_n]
                              : make_float4(0,0,0,0);
        }
        #pragma unroll
        for (int kk = 0; kk < BK; kk++) {
            float a[TM];
            if (TM == 4) {
                float4 v = *(const float4*)&sA[buf][kk][ty*4];
                a[0]=v.x; a[1]=v.y; a[2]=v.z; a[3]=v.w;
            } else {
                float2 v = *(const float2*)&sA[buf][kk][ty*2];
                a[0]=v.x; a[1]=v.y;
            }
            ulonglong2 wp = *(const ulonglong2*)&sW[buf][kk][tx*4];
            #pragma unroll
            for (int i = 0; i < TM; i++) {
                unsigned long long ad = bcast2(a[i]);
                fma2(acc2[i][0], ad, wp.x);
                fma2(acc2[i][1], ad, wp.y);
            }
        }
        if (t + 1 < KT) {
            int nb = buf ^ 1;
            if (aload) {
                sA[nb][a_k+0][a_m] = av.x; sA[nb][a_k+1][a_m] = av.y;
                sA[nb][a_k+2][a_m] = av.z; sA[nb][a_k+3][a_m] = av.w;
            }
            *(float4*)&sW[nb][w_k][w_n] = wv;
            __syncthreads();
        }
    }

    float4 bv = *(const float4*)&bias[col0 + tx*4];
    #pragma unroll
    for (int i = 0; i < TM; i++) {
        float c0, c1, c2, c3;
        unpack2(c0, c1, acc2[i][0]);
        unpack2(c2, c3, acc2[i][1]);
        float4 v = make_float4(c0 + bv.x, c1 + bv.y, c2 + bv.z, c3 + bv.w);
        *(float4*)&C[(size_t)(row0 + ty*TM + i)*N + col0 + tx*4] = v;
    }
}

__device__ __forceinline__ float gelu_exact(float z) {
    return 0.5f * z * (1.0f + erff(z * SQRT1_2));
}

// ---------------- MEGA helpers (plain functions, no macros) ----------------
__device__ __forceinline__ void mega_pref(float wb[16], const float* __restrict__ wcol, int t) {
    #pragma unroll
    for (int i = 0; i < 16; i++)
        wb[i] = __ldg(&wcol[(size_t)(t*16 + i)*HID2]);
}

__device__ __forceinline__ void mega_chunk(unsigned long long acc2[8],
                                           const float (* __restrict__ sA)[INC],
                                           const float wb[16], int t) {
    #pragma unroll
    for (int kk = 0; kk < 16; kk += 4) {
        unsigned long long wd0 = pack2(wb[kk+0], wb[kk+1]);
        unsigned long long wd1 = pack2(wb[kk+2], wb[kk+3]);
        #pragma unroll
        for (int r = 0; r < 8; r++) {
            ulonglong2 ap = *(const ulonglong2*)&sA[r][t*16 + kk];
            fma2(acc2[r], ap.x, wd0);
            fma2(acc2[r], ap.y, wd1);
        }
    }
}

// ---------------- MEGA v4: LN1+GELU -> GEMM(W2)+b2 -> LN2+GELU -> w3 -------
// 128 blocks x 256 threads. Thread owns 1 column (tid) x 8 rows.
// W2 column streamed via deep register double-buffer (16 loads in flight,
// barrier-free main loop) -> L2 latency covered by compute.
__global__ void __launch_bounds__(256) k_mega(
    const float* __restrict__ gt1,
    const float* __restrict__ g1v, const float* __restrict__ be1,
    const float* __restrict__ w2,  const float* __restrict__ b2,
    const float* __restrict__ g2v, const float* __restrict__ be2,
    const float* __restrict__ w3,  const float* __restrict__ b3,
    const float* __restrict__ mask, float* __restrict__ rend)
{
    __shared__ float sA[8][INC];                 // 16 KB (post LN1+GELU)

    int tid = threadIdx.x, warp = tid >> 5, lane = tid & 31;
    int row0 = blockIdx.x * 8;
    int row = row0 + warp;

    // ---- LN1 + GELU (warp-private: each warp its own row) ----
    {
        const float4* xr = (const float4*)(gt1 + (size_t)row*INC);
        float4 v[4]; float s = 0.0f;
        #pragma unroll
        for (int i = 0; i < 4; i++) {
            v[i] = xr[lane + 32*i];
            s += v[i].x + v[i].y + v[i].z + v[i].w;
        }
        #pragma unroll
        for (int o = 16; o; o >>= 1) s += __shfl_xor_sync(0xffffffff, s, o);
        float m = s * (1.0f/INC);
        float var = 0.0f;
        #pragma unroll
        for (int i = 0; i < 4; i++) {
            float dx=v[i].x-m, dy=v[i].y-m, dz=v[i].z-m, dw=v[i].w-m;
            var += dx*dx + dy*dy + dz*dz + dw*dw;
        }
        #pragma unroll
        for (int o = 16; o; o >>= 1) var += __shfl_xor_sync(0xffffffff, var, o);
        float inv = rsqrtf(var * (1.0f/INC) + 1e-5f);
        #pragma unroll
        for (int i = 0; i < 4; i++) {
            int c4 = lane + 32*i;
            float4 gg = ((const float4*)g1v)[c4];
            float4 ee = ((const float4*)be1)[c4];
            float4 o4;
            o4.x = gelu_exact((v[i].x - m)*inv*gg.x + ee.x);
            o4.y = gelu_exact((v[i].y - m)*inv*gg.y + ee.y);
            o4.z = gelu_exact((v[i].z - m)*inv*gg.z + ee.z);
            o4.w = gelu_exact((v[i].w - m)*inv*gg.w + ee.w);
            ((float4*)sA[warp])[c4] = o4;
        }
    }
    __syncthreads();   // sA complete

    // ---- GEMM: barrier-free, deep reg-double-buffered W prefetch ----
    unsigned long long acc2[8];
    #pragma unroll
    for (int r = 0; r < 8; r++) acc2[r] = 0ull;

    const float* wcol = w2 + tid;   // this thread's W2 column
    float wb0[16], wb1[16];
    mega_pref(wb0, wcol, 0);
    #pragma unroll 1
    for (int t = 0; t < 32; t += 2) {
        if (t + 1 < 32) mega_pref(wb1, wcol, t + 1);
        mega_chunk(acc2, sA, wb0, t);
        if (t + 2 < 32) mega_pref(wb0, wcol, t + 2);
        if (t + 1 < 32) mega_chunk(acc2, sA, wb1, t + 1);
    }

    // ---- unpack + bias ----
    float c[8];
    float b2v = b2[tid];
    #pragma unroll
    for (int r = 0; r < 8; r++) {
        float lo, hi;
        unpack2(lo, hi, acc2[r]);
        c[r] = lo + hi + b2v;
    }

    // ---- stage through smem (reuse sA): sOut[r][col] ----
    float* sOut = &sA[0][0];
    __syncthreads();   // all GEMM reads of sA complete
    #pragma unroll
    for (int r = 0; r < 8; r++) sOut[r*HID2 + tid] = c[r];
    __syncthreads();

    // ---- warp w: LN2 + GELU + w3 projection for row (row0 + w) ----
    float cc[8];
    {
        float4 cA = *(const float4*)&sOut[warp*HID2 + lane*8];
        float4 cB = *(const float4*)&sOut[warp*HID2 + lane*8 + 4];
        cc[0]=cA.x; cc[1]=cA.y; cc[2]=cA.z; cc[3]=cA.w;
        cc[4]=cB.x; cc[5]=cB.y; cc[6]=cB.z; cc[7]=cB.w;
    }
    float s2 = 0.0f;
    #pragma unroll
    for (int j = 0; j < 8; j++) s2 += cc[j];
    #pragma unroll
    for (int o = 16; o; o >>= 1) s2 += __shfl_xor_sync(0xffffffff, s2, o);
    float m2 = s2 * (1.0f/HID2);
    float v2 = 0.0f;
    #pragma unroll
    for (int j = 0; j < 8; j++) { float d = cc[j]-m2; v2 += d*d; }
    #pragma unroll
    for (int o = 16; o; o >>= 1) v2 += __shfl_xor_sync(0xffffffff, v2, o);
    float inv2 = rsqrtf(v2 * (1.0f/HID2) + 1e-5f);

    float h[8];
    {
        float4 gA = ((const float4*)g2v)[lane*2], gB = ((const float4*)g2v)[lane*2+1];
        float4 eA = ((const float4*)be2)[lane*2], eB = ((const float4*)be2)[lane*2+1];
        float gs[8] = {gA.x,gA.y,gA.z,gA.w,gB.x,gB.y,gB.z,gB.w};
        float es[8] = {eA.x,eA.y,eA.z,eA.w,eB.x,eB.y,eB.z,eB.w};
        #pragma unroll
        for (int j = 0; j < 8; j++)
            h[j] = gelu_exact((cc[j]-m2)*inv2*gs[j] + es[j]);
    }
    float a0 = 0.0f, a1 = 0.0f;
    #pragma unroll
    for (int j = 0; j < 4; j++) {
        float4 w = ((const float4*)w3)[lane*4 + j];   // rows lane*8+2j, +2j+1
        a0 += h[2*j]*w.x + h[2*j+1]*w.z;
        a1 += h[2*j]*w.y + h[2*j+1]*w.w;
    }
    #pragma unroll
    for (int o = 16; o; o >>= 1) {
        a0 += __shfl_xor_sync(0xffffffff, a0, o);
        a1 += __shfl_xor_sync(0xffffffff, a1, o);
    }
    if (lane == 0) {
        int b = row >> 7, n = row & 127;
        float c0 = g_feat[(size_t)row*KFP + 0];
        float c1 = g_feat[(size_t)row*KFP + 1];
        float m0 = mask[(size_t)(b*COUT + 0)*NPTS + n];
        float m1 = mask[(size_t)(b*COUT + 1)*NPTS + n];
        rend[(size_t)(b*COUT + 0)*NPTS + n] = (a0 + b3[0])*m0 + c0;
        rend[(size_t)(b*COUT + 1)*NPTS + n] = (a1 + b3[1])*m1 + c1;
    }
}

// ---------------- launch ----------------
extern "C" void kernel_launch(void* const* d_in, const int* in_sizes, int n_in,
                              void* d_out, int out_size)
{
    const float* res2       = (const float*)d_in[1];
    const float* out        = (const float*)d_in[2];
    const float* over_gen   = (const float*)d_in[3];
    const float* rand_point = (const float*)d_in[4];
    const float* mask       = (const float*)d_in[5];
    const float* w1  = (const float*)d_in[6];
    const float* b1  = (const float*)d_in[7];
    const float* g1  = (const float*)d_in[8];
    const float* be1 = (const float*)d_in[9];
    const float* w2  = (const float*)d_in[10];
    const float* b2  = (const float*)d_in[11];
    const float* g2  = (const float*)d_in[12];
    const float* be2 = (const float*)d_in[13];
    const float* w3  = (const float*)d_in[14];
    const float* b3  = (const float*)d_in[15];

    float* o_rend = (float*)d_out;                      // [8,2,128]
    float* o_pts  = o_rend + (size_t)BATCH*COUT*NPTS;   // [8,128,2]

    float* gf;  cudaGetSymbolAddress((void**)&gf,  g_feat);
    float* gt1; cudaGetSymbolAddress((void**)&gt1, g_t1);

    k_points<<<BATCH, NOG>>>(out, over_gen, rand_point, o_pts);
    k_feat  <<<BATCH*NPTS, 128>>>(out, res2);

    dim3 g1g(INC/64, NROWS/64);
    k_gemm<KFEAT, KFP, KFP, INC, 64, 4><<<g1g, 256>>>(gf, w1, b1, gt1);

    k_mega<<<NROWS/8, 256>>>(gt1, g1, be1, w2, b2, g2, be2, w3, b3, mask, o_rend);
}

// round 15
// speedup vs baseline: 1.1891x; 1.0983x over previous
#include <cuda_runtime.h>
#include <math.h>

#define BATCH 8
#define HF    128
#define PIX   (HF*HF)
#define NOG   384
#define NIMP  96
#define NPTS  128
#define INC   512
#define HID2  256
#define KFEAT 514
#define KFP   528
#define COUT  2
#define NROWS (BATCH*NPTS) // 1024
#define SQRT1_2 0.70710678118654752440f

// ---------------- bilinear helper ----------------
struct Bilin { int l00,l10,l01,l11; float w00,w10,w01,w11; };

__device__ __forceinline__ Bilin make_bilin(float px, float py) {
    Bilin r;
    float gx = ((2.0f*px - 1.0f + 1.0f)*(float)HF - 1.0f)*0.5f;
    float gy = ((2.0f*py - 1.0f + 1.0f)*(float)HF - 1.0f)*0.5f;
    float x0f = floorf(gx), y0f = floorf(gy);
    float wx1 = gx - x0f,  wy1 = gy - y0f;
    float wx0 = 1.0f - wx1, wy0 = 1.0f - wy1;
    int x0 = (int)x0f, y0 = (int)y0f;
    int x1 = x0 + 1,   y1 = y0 + 1;
    bool vx0 = (x0 >= 0) && (x0 <= HF-1);
    bool vx1 = (x1 >= 0) && (x1 <= HF-1);
    bool vy0 = (y0 >= 0) && (y0 <= HF-1);
    bool vy1 = (y1 >= 0) && (y1 <= HF-1);
    int x0c = min(max(x0,0),HF-1), x1c = min(max(x1,0),HF-1);
    int y0c = min(max(y0,0),HF-1), y1c = min(max(y1,0),HF-1);
    r.l00 = y0c*HF + x0c;  r.l10 = y0c*HF + x1c;
    r.l01 = y1c*HF + x0c;  r.l11 = y1c*HF + x1c;
    r.w00 = (vx0 && vy0) ? wx0*wy0 : 0.0f;
    r.w10 = (vx1 && vy0) ? wx1*wy0 : 0.0f;
    r.w01 = (vx0 && vy1) ? wx0*wy1 : 0.0f;
    r.w11 = (vx1 && vy1) ? wx1*wy1 : 0.0f;
    return r;
}

// ---------------- packed f32x2 helpers ----------------
__device__ __forceinline__ void fma2(unsigned long long& d,
                                     unsigned long long a, unsigned long long b) {
    asm("fma.rn.f32x2 %0, %1, %2, %0;" : "+l"(d) : "l"(a), "l"(b));
}
__device__ __forceinline__ unsigned long long pack2(float lo, float hi) {
    unsigned long long d;
    asm("mov.b64 %0, {%1, %2};" : "=l"(d) : "f"(lo), "f"(hi));
    return d;
}
__device__ __forceinline__ void unpack2(float& lo, float& hi, unsigned long long d) {
    asm("mov.b64 {%0, %1}, %2;" : "=f"(lo), "=f"(hi) : "l"(d));
}

__device__ __forceinline__ float gelu_exact(float z) {
    return 0.5f * z * (1.0f + erff(z * SQRT1_2));
}

// ============================================================================
// ONE kernel: points -> feat gather -> gemm1+LN1+GELU -> gemm2+LN2+GELU
//             -> w3 proj + mask + coarse.  Block = 8 rows of one batch.
// ============================================================================
__global__ void __launch_bounds__(256, 1) k_all(
    const float* __restrict__ out,  const float* __restrict__ res2,
    const float* __restrict__ over_gen, const float* __restrict__ rand_point,
    const float* __restrict__ mask,
    const float* __restrict__ w1, const float* __restrict__ b1,
    const float* __restrict__ g1v, const float* __restrict__ be1,
    const float* __restrict__ w2, const float* __restrict__ b2,
    const float* __restrict__ g2v, const float* __restrict__ be2,
    const float* __restrict__ w3, const float* __restrict__ b3,
    float* __restrict__ rend, float* __restrict__ pts_out)
{
    __shared__ float  sA[8][KFP];      // feat -> gt1 -> h1 -> gt2 staging
    __shared__ float  s_unc[NOG];
    __shared__ float2 spts[8];
    __shared__ float  scoarse[8][2];

    int tid = threadIdx.x, warp = tid >> 5, lane = tid & 31;
    int blk = blockIdx.x;
    int b  = blk >> 4;          // batch
    int bi = blk & 15;          // block-in-batch
    int n0 = bi * 8;            // first point index within batch
    int row0 = b*NPTS + n0;

    // ---------------- Phase A: this block's 8 sampling points --------------
    if (bi < 12) {                       // importance rows [n0, n0+8) < 96
        const float* ob = out + (size_t)b*2*PIX;
        const float2* og = (const float2*)over_gen + (size_t)b*NOG;
        for (int j = tid; j < NOG; j += 256) {
            float2 p = og[j];
            Bilin bl = make_bilin(p.x, p.y);
            float a00 = ob[bl.l00], b00 = ob[PIX + bl.l00];
            float a10 = ob[bl.l10], b10 = ob[PIX + bl.l10];
            float a01 = ob[bl.l01], b01 = ob[PIX + bl.l01];
            float a11 = ob[bl.l11], b11 = ob[PIX + bl.l11];
            float og0 = bl.w00*fmaxf(a00,b00) + bl.w10*fmaxf(a10,b10)
                      + bl.w01*fmaxf(a01,b01) + bl.w11*fmaxf(a11,b11);
            float og1 = bl.w00*fminf(a00,b00) + bl.w10*fminf(a10,b10)
                      + bl.w01*fminf(a01,b01) + bl.w11*fminf(a11,b11);
            s_unc[j] = og1 - og0;        // == -(og0 - og1)
        }
        __syncthreads();
        for (int j = tid; j < NOG; j += 256) {
            float u = s_unc[j];
            int rank = 0;
            #pragma unroll 4
            for (int i = 0; i < NOG; i++) {
                float ui = s_unc[i];
                rank += (ui > u) || (ui == u && i < j);   // stable
            }
            if (rank >= n0 && rank < n0 + 8)
                spts[rank - n0] = og[j];
        }
    } else if (bi < 14) {                // coverage rows: provably (0,0)
        if (tid < 8) spts[tid] = make_float2(0.f, 0.f);
    } else {                             // rand rows
        if (tid < 8)
            spts[tid] = ((const float2*)rand_point)[b*16 + (n0 - 112) + tid];
    }
    __syncthreads();
    if (tid < 8) ((float2*)pts_out)[row0 + tid] = spts[tid];

    // ---------------- Phase B: feat gather (warp per row) ------------------
    {
        float2 p = spts[warp];
        Bilin bl = make_bilin(p.x, p.y);
        const float* rb = res2 + (size_t)b*INC*PIX;
        #pragma unroll 4
        for (int c = lane; c < INC; c += 32) {
            const float* pp = rb + (size_t)c*PIX;
            sA[warp][2 + c] = bl.w00*pp[bl.l00] + bl.w10*pp[bl.l10]
                            + bl.w01*pp[bl.l01] + bl.w11*pp[bl.l11];
        }
        if (lane < 2) {
            const float* pp = out + (size_t)(b*2 + lane)*PIX;
            float cv = bl.w00*pp[bl.l00] + bl.w10*pp[bl.l10]
                     + bl.w01*pp[bl.l01] + bl.w11*pp[bl.l11];
            sA[warp][lane] = cv;
            scoarse[warp][lane] = cv;
        }
    }
    __syncthreads();

    // ---------------- Phase C: gemm1 + b1 (thread = cols 2t,2t+1 x 8 rows) -
    int c0 = tid * 2;
    unsigned long long accA[8], accB[8];
    #pragma unroll
    for (int r = 0; r < 8; r++) { accA[r] = 0ull; accB[r] = 0ull; }

    #pragma unroll 1
    for (int k8 = 0; k8 < 512; k8 += 8) {
        float2 wp[8];
        #pragma unroll
        for (int i = 0; i < 8; i++)
            wp[i] = *(const float2*)&w1[(size_t)(k8 + i)*INC + c0];
        #pragma unroll
        for (int kk = 0; kk < 8; kk += 4) {
            unsigned long long wa0 = pack2(wp[kk].x, wp[kk+1].x);
            unsigned long long wa1 = pack2(wp[kk+2].x, wp[kk+3].x);
            unsigned long long wb0 = pack2(wp[kk].y, wp[kk+1].y);
            unsigned long long wb1 = pack2(wp[kk+2].y, wp[kk+3].y);
            #pragma unroll
            for (int r = 0; r < 8; r++) {
                ulonglong2 ap = *(const ulonglong2*)&sA[r][k8 + kk];
                fma2(accA[r], ap.x, wa0); fma2(accA[r], ap.y, wa1);
                fma2(accB[r], ap.x, wb0); fma2(accB[r], ap.y, wb1);
            }
        }
    }
    {   // tail k = 512, 513
        float2 w512 = *(const float2*)&w1[(size_t)512*INC + c0];
        float2 w513 = *(const float2*)&w1[(size_t)513*INC + c0];
        unsigned long long wa = pack2(w512.x, w513.x);
        unsigned long long wb = pack2(w512.y, w513.y);
        #pragma unroll
        for (int r = 0; r < 8; r++) {
            unsigned long long ap = *(const unsigned long long*)&sA[r][512];
            fma2(accA[r], ap, wa);
            fma2(accB[r], ap, wb);
        }
    }
    float rA[8], rB[8];
    {
        float b1a = b1[c0], b1b = b1[c0 + 1];
        #pragma unroll
        for (int r = 0; r < 8; r++) {
            float lo, hi;
            unpack2(lo, hi, accA[r]); rA[r] = lo + hi + b1a;
            unpack2(lo, hi, accB[r]); rB[r] = lo + hi + b1b;
        }
    }
    __syncthreads();   // all feat reads done
    #pragma unroll
    for (int r = 0; r < 8; r++)
        *(float2*)&sA[r][c0] = make_float2(rA[r], rB[r]);
    __syncthreads();

    // ---------------- Phase D: LN1 + GELU (warp per row, in place) ---------
    {
        float4* xr = (float4*)sA[warp];
        float4 v[4]; float s = 0.0f;
        #pragma unroll
        for (int i = 0; i < 4; i++) {
            v[i] = xr[lane + 32*i];
            s += v[i].x + v[i].y + v[i].z + v[i].w;
        }
        #pragma unroll
        for (int o = 16; o; o >>= 1) s += __shfl_xor_sync(0xffffffff, s, o);
        float m = s * (1.0f/INC);
        float var = 0.0f;
        #pragma unroll
        for (int i = 0; i < 4; i++) {
            float dx=v[i].x-m, dy=v[i].y-m, dz=v[i].z-m, dw=v[i].w-m;
            var += dx*dx + dy*dy + dz*dz + dw*dw;
        }
        #pragma unroll
        for (int o = 16; o; o >>= 1) var += __shfl_xor_sync(0xffffffff, var, o);
        float inv = rsqrtf(var * (1.0f/INC) + 1e-5f);
        #pragma unroll
        for (int i = 0; i < 4; i++) {
            int c4 = lane + 32*i;
            float4 gg = ((const float4*)g1v)[c4];
            float4 ee = ((const float4*)be1)[c4];
            float4 o4;
            o4.x = gelu_exact((v[i].x - m)*inv*gg.x + ee.x);
            o4.y = gelu_exact((v[i].y - m)*inv*gg.y + ee.y);
            o4.z = gelu_exact((v[i].z - m)*inv*gg.z + ee.z);
            o4.w = gelu_exact((v[i].w - m)*inv*gg.w + ee.w);
            xr[c4] = o4;
        }
    }
    __syncthreads();

    // ---------------- Phase E: gemm2 + b2 (thread = col tid x 8 rows) ------
    unsigned long long acc[8];
    #pragma unroll
    for (int r = 0; r < 8; r++) acc[r] = 0ull;
    {
        const float* wcol = w2 + tid;
        #pragma unroll 1
        for (int k8 = 0; k8 < 512; k8 += 8) {
            float wv[8];
            #pragma unroll
            for (int i = 0; i < 8; i++)
                wv[i] = __ldg(&wcol[(size_t)(k8 + i)*HID2]);
            #pragma unroll
            for (int kk = 0; kk < 8; kk += 4) {
                unsigned long long wd0 = pack2(wv[kk+0], wv[kk+1]);
                unsigned long long wd1 = pack2(wv[kk+2], wv[kk+3]);
                #pragma unroll
                for (int r = 0; r < 8; r++) {
                    ulonglong2 ap = *(const ulonglong2*)&sA[r][k8 + kk];
                    fma2(acc[r], ap.x, wd0);
                    fma2(acc[r], ap.y, wd1);
                }
            }
        }
    }
    float c[8];
    {
        float b2v = b2[tid];
        #pragma unroll
        for (int r = 0; r < 8; r++) {
            float lo, hi;
            unpack2(lo, hi, acc[r]);
            c[r] = lo + hi + b2v;
        }
    }
    __syncthreads();   // all h1 reads done
    #pragma unroll
    for (int r = 0; r < 8; r++) sA[r][tid] = c[r];
    __syncthreads();

    // ---------------- Phase F: LN2 + GELU + w3 + mask + coarse -------------
    float cc[8];
    {
        float4 cA = *(const float4*)&sA[warp][lane*8];
        float4 cB = *(const float4*)&sA[warp][lane*8 + 4];
        cc[0]=cA.x; cc[1]=cA.y; cc[2]=cA.z; cc[3]=cA.w;
        cc[4]=cB.x; cc[5]=cB.y; cc[6]=cB.z; cc[7]=cB.w;
    }
    float s2 = 0.0f;
    #pragma unroll
    for (int j = 0; j < 8; j++) s2 += cc[j];
    #pragma unroll
    for (int o = 16; o; o >>= 1) s2 += __shfl_xor_sync(0xffffffff, s2, o);
    float m2 = s2 * (1.0f/HID2);
    float v2 = 0.0f;
    #pragma unroll
    for (int j = 0; j < 8; j++) { float d = cc[j]-m2; v2 += d*d; }
    #pragma unroll
    for (int o = 16; o; o >>= 1) v2 += __shfl_xor_sync(0xffffffff, v2, o);
    float inv2 = rsqrtf(v2 * (1.0f/HID2) + 1e-5f);

    float h[8];
    {
        float4 gA = ((const float4*)g2v)[lane*2], gB = ((const float4*)g2v)[lane*2+1];
        float4 eA = ((const float4*)be2)[lane*2], eB = ((const float4*)be2)[lane*2+1];
        float gs[8] = {gA.x,gA.y,gA.z,gA.w,gB.x,gB.y,gB.z,gB.w};
        float es[8] = {eA.x,eA.y,eA.z,eA.w,eB.x,eB.y,eB.z,eB.w};
        #pragma unroll
        for (int j = 0; j < 8; j++)
            h[j] = gelu_exact((cc[j]-m2)*inv2*gs[j] + es[j]);
    }
    float a0 = 0.0f, a1 = 0.0f;
    #pragma unroll
    for (int j = 0; j < 4; j++) {
        float4 w = ((const float4*)w3)[lane*4 + j];   // rows lane*8+2j, +2j+1
        a0 += h[2*j]*w.x + h[2*j+1]*w.z;
        a1 += h[2*j]*w.y + h[2*j+1]*w.w;
    }
    #pragma unroll
    for (int o = 16; o; o >>= 1) {
        a0 += __shfl_xor_sync(0xffffffff, a0, o);
        a1 += __shfl_xor_sync(0xffffffff, a1, o);
    }
    if (lane == 0) {
        int n = n0 + warp;
        float cv0 = scoarse[warp][0], cv1 = scoarse[warp][1];
        float m0 = mask[(size_t)(b*COUT + 0)*NPTS + n];
        float m1 = mask[(size_t)(b*COUT + 1)*NPTS + n];
        rend[(size_t)(b*COUT + 0)*NPTS + n] = (a0 + b3[0])*m0 + cv0;
        rend[(size_t)(b*COUT + 1)*NPTS + n] = (a1 + b3[1])*m1 + cv1;
    }
}

// ---------------- launch: ONE kernel ----------------
extern "C" void kernel_launch(void* const* d_in, const int* in_sizes, int n_in,
                              void* d_out, int out_size)
{
    const float* res2       = (const float*)d_in[1];
    const float* out        = (const float*)d_in[2];
    const float* over_gen   = (const float*)d_in[3];
    const float* rand_point = (const float*)d_in[4];
    const float* mask       = (const float*)d_in[5];
    const float* w1  = (const float*)d_in[6];
    const float* b1  = (const float*)d_in[7];
    const float* g1  = (const float*)d_in[8];
    const float* be1 = (const float*)d_in[9];
    const float* w2  = (const float*)d_in[10];
    const float* b2  = (const float*)d_in[11];
    const float* g2  = (const float*)d_in[12];
    const float* be2 = (const float*)d_in[13];
    const float* w3  = (const float*)d_in[14];
    const float* b3  = (const float*)d_in[15];

    float* o_rend = (float*)d_out;                      // [8,2,128]
    float* o_pts  = o_rend + (size_t)BATCH*COUT*NPTS;   // [8,128,2]

    k_all<<<NROWS/8, 256>>>(out, res2, over_gen, rand_point, mask,
                            w1, b1, g1, be1, w2, b2, g2, be2, w3, b3,
                            o_rend, o_pts);
}

// round 16
// speedup vs baseline: 1.4450x; 1.2152x over previous
#include <cuda_runtime.h>
#include <math.h>

#define BATCH 8
#define HF    128
#define PIX   (HF*HF)
#define NOG   384
#define NIMP  96
#define NPTS  128
#define INC   512
#define HID2  256
#define KFEAT 514
#define KFP   528
#define COUT  2
#define NROWS (BATCH*NPTS) // 1024
#define RPB   4            // rows per block
#define SQRT1_2 0.70710678118654752440f

// ---------------- bilinear helper ----------------
struct Bilin { int l00,l10,l01,l11; float w00,w10,w01,w11; };

__device__ __forceinline__ Bilin make_bilin(float px, float py) {
    Bilin r;
    float gx = ((2.0f*px - 1.0f + 1.0f)*(float)HF - 1.0f)*0.5f;
    float gy = ((2.0f*py - 1.0f + 1.0f)*(float)HF - 1.0f)*0.5f;
    float x0f = floorf(gx), y0f = floorf(gy);
    float wx1 = gx - x0f,  wy1 = gy - y0f;
    float wx0 = 1.0f - wx1, wy0 = 1.0f - wy1;
    int x0 = (int)x0f, y0 = (int)y0f;
    int x1 = x0 + 1,   y1 = y0 + 1;
    bool vx0 = (x0 >= 0) && (x0 <= HF-1);
    bool vx1 = (x1 >= 0) && (x1 <= HF-1);
    bool vy0 = (y0 >= 0) && (y0 <= HF-1);
    bool vy1 = (y1 >= 0) && (y1 <= HF-1);
    int x0c = min(max(x0,0),HF-1), x1c = min(max(x1,0),HF-1);
    int y0c = min(max(y0,0),HF-1), y1c = min(max(y1,0),HF-1);
    r.l00 = y0c*HF + x0c;  r.l10 = y0c*HF + x1c;
    r.l01 = y1c*HF + x0c;  r.l11 = y1c*HF + x1c;
    r.w00 = (vx0 && vy0) ? wx0*wy0 : 0.0f;
    r.w10 = (vx1 && vy0) ? wx1*wy0 : 0.0f;
    r.w01 = (vx0 && vy1) ? wx0*wy1 : 0.0f;
    r.w11 = (vx1 && vy1) ? wx1*wy1 : 0.0f;
    return r;
}

// ---------------- packed f32x2 helpers ----------------
__device__ __forceinline__ void fma2(unsigned long long& d,
                                     unsigned long long a, unsigned long long b) {
    asm("fma.rn.f32x2 %0, %1, %2, %0;" : "+l"(d) : "l"(a), "l"(b));
}
__device__ __forceinline__ unsigned long long pack2(float lo, float hi) {
    unsigned long long d;
    asm("mov.b64 %0, {%1, %2};" : "=l"(d) : "f"(lo), "f"(hi));
    return d;
}
__device__ __forceinline__ void unpack2(float& lo, float& hi, unsigned long long d) {
    asm("mov.b64 {%0, %1}, %2;" : "=f"(lo), "=f"(hi) : "l"(d));
}

__device__ __forceinline__ float gelu_exact(float z) {
    return 0.5f * z * (1.0f + erff(z * SQRT1_2));
}

// ============================================================================
// ONE kernel, 4 rows per block, 256 blocks, 2 blocks/SM.
// points -> feat gather -> gemm1+LN1+GELU -> gemm2+LN2+GELU -> w3+mask+coarse
// ============================================================================
__global__ void __launch_bounds__(256, 2) k_all(
    const float* __restrict__ out,  const float* __restrict__ res2,
    const float* __restrict__ over_gen, const float* __restrict__ rand_point,
    const float* __restrict__ mask,
    const float* __restrict__ w1, const float* __restrict__ b1,
    const float* __restrict__ g1v, const float* __restrict__ be1,
    const float* __restrict__ w2, const float* __restrict__ b2,
    const float* __restrict__ g2v, const float* __restrict__ be2,
    const float* __restrict__ w3, const float* __restrict__ b3,
    float* __restrict__ rend, float* __restrict__ pts_out)
{
    __shared__ float  sA[RPB][KFP];      // feat -> h1 -> gt2 staging
    __shared__ float  s_unc[NOG];
    __shared__ float2 spts[RPB];
    __shared__ float  scoarse[RPB][2];

    int tid = threadIdx.x, warp = tid >> 5, lane = tid & 31;
    int blk = blockIdx.x;
    int b  = blk >> 5;          // batch (32 blocks per batch)
    int bi = blk & 31;          // block-in-batch
    int n0 = bi * RPB;          // first point index within batch
    int row0 = b*NPTS + n0;

    // ---------------- Phase A: this block's 4 sampling points --------------
    if (bi < 24) {                       // importance rows: n0+3 < 96
        const float* ob = out + (size_t)b*2*PIX;
        const float2* og = (const float2*)over_gen + (size_t)b*NOG;
        for (int j = tid; j < NOG; j += 256) {
            float2 p = og[j];
            Bilin bl = make_bilin(p.x, p.y);
            float a00 = ob[bl.l00], b00 = ob[PIX + bl.l00];
            float a10 = ob[bl.l10], b10 = ob[PIX + bl.l10];
            float a01 = ob[bl.l01], b01 = ob[PIX + bl.l01];
            float a11 = ob[bl.l11], b11 = ob[PIX + bl.l11];
            float og0 = bl.w00*fmaxf(a00,b00) + bl.w10*fmaxf(a10,b10)
                      + bl.w01*fmaxf(a01,b01) + bl.w11*fmaxf(a11,b11);
            float og1 = bl.w00*fminf(a00,b00) + bl.w10*fminf(a10,b10)
                      + bl.w01*fminf(a01,b01) + bl.w11*fminf(a11,b11);
            s_unc[j] = og1 - og0;        // == -(og0 - og1)
        }
        __syncthreads();
        for (int j = tid; j < NOG; j += 256) {
            float u = s_unc[j];
            int rank = 0;
            #pragma unroll 4
            for (int i = 0; i < NOG; i++) {
                float ui = s_unc[i];
                rank += (ui > u) || (ui == u && i < j);   // stable
            }
            if (rank >= n0 && rank < n0 + RPB)
                spts[rank - n0] = og[j];
        }
    } else if (bi < 28) {                // coverage rows: provably (0,0)
        if (tid < RPB) spts[tid] = make_float2(0.f, 0.f);
    } else {                             // rand rows
        if (tid < RPB)
            spts[tid] = ((const float2*)rand_point)[b*16 + (n0 - 112) + tid];
    }
    __syncthreads();
    if (tid < RPB) ((float2*)pts_out)[row0 + tid] = spts[tid];

    // ---------------- Phase B: feat gather (2 warps per row) ---------------
    {
        int rrow = warp & 3, half = warp >> 2;       // half 0: ch 0-255, 1: 256-511
        float2 p = spts[rrow];
        Bilin bl = make_bilin(p.x, p.y);
        const float* rb = res2 + (size_t)b*INC*PIX;
        #pragma unroll
        for (int i = 0; i < 8; i++) {
            int c = half*256 + lane + 32*i;
            const float* pp = rb + (size_t)c*PIX;
            sA[rrow][2 + c] = bl.w00*pp[bl.l00] + bl.w10*pp[bl.l10]
                            + bl.w01*pp[bl.l01] + bl.w11*pp[bl.l11];
        }
        if (half == 0 && lane < 2) {
            const float* pp = out + (size_t)(b*2 + lane)*PIX;
            float cv = bl.w00*pp[bl.l00] + bl.w10*pp[bl.l10]
                     + bl.w01*pp[bl.l01] + bl.w11*pp[bl.l11];
            sA[rrow][lane] = cv;
            scoarse[rrow][lane] = cv;
        }
    }
    __syncthreads();

    // ---------------- Phase C: gemm1 + b1 (thread = cols 2t,2t+1 x 4 rows) -
    int c0 = tid * 2;
    unsigned long long accA[RPB], accB[RPB];
    #pragma unroll
    for (int r = 0; r < RPB; r++) { accA[r] = 0ull; accB[r] = 0ull; }

    {
        float2 wp[8], wn[8];
        #pragma unroll
        for (int i = 0; i < 8; i++)
            wp[i] = *(const float2*)&w1[(size_t)i*INC + c0];
        #pragma unroll 1
        for (int k8 = 0; k8 < 512; k8 += 8) {
            if (k8 + 8 < 512) {
                #pragma unroll
                for (int i = 0; i < 8; i++)
                    wn[i] = *(const float2*)&w1[(size_t)(k8 + 8 + i)*INC + c0];
            }
            #pragma unroll
            for (int kk = 0; kk < 8; kk += 4) {
                unsigned long long wa0 = pack2(wp[kk].x, wp[kk+1].x);
                unsigned long long wa1 = pack2(wp[kk+2].x, wp[kk+3].x);
                unsigned long long wb0 = pack2(wp[kk].y, wp[kk+1].y);
                unsigned long long wb1 = pack2(wp[kk+2].y, wp[kk+3].y);
                #pragma unroll
                for (int r = 0; r < RPB; r++) {
                    ulonglong2 ap = *(const ulonglong2*)&sA[r][k8 + kk];
                    fma2(accA[r], ap.x, wa0); fma2(accA[r], ap.y, wa1);
                    fma2(accB[r], ap.x, wb0); fma2(accB[r], ap.y, wb1);
                }
            }
            #pragma unroll
            for (int i = 0; i < 8; i++) wp[i] = wn[i];
        }
    }
    {   // tail k = 512, 513
        float2 w512 = *(const float2*)&w1[(size_t)512*INC + c0];
        float2 w513 = *(const float2*)&w1[(size_t)513*INC + c0];
        unsigned long long wa = pack2(w512.x, w513.x);
        unsigned long long wb = pack2(w512.y, w513.y);
        #pragma unroll
        for (int r = 0; r < RPB; r++) {
            unsigned long long ap = *(const unsigned long long*)&sA[r][512];
            fma2(accA[r], ap, wa);
            fma2(accB[r], ap, wb);
        }
    }
    float rA[RPB], rB[RPB];
    {
        float b1a = b1[c0], b1b = b1[c0 + 1];
        #pragma unroll
        for (int r = 0; r < RPB; r++) {
            float lo, hi;
            unpack2(lo, hi, accA[r]); rA[r] = lo + hi + b1a;
            unpack2(lo, hi, accB[r]); rB[r] = lo + hi + b1b;
        }
    }
    __syncthreads();   // all feat reads done
    #pragma unroll
    for (int r = 0; r < RPB; r++)
        *(float2*)&sA[r][c0] = make_float2(rA[r], rB[r]);
    __syncthreads();

    // ---------------- Phase D: LN1 + GELU (warp per row, warps 0-3) --------
    if (warp < RPB) {
        float4* xr = (float4*)sA[warp];
        float4 v[4]; float s = 0.0f;
        #pragma unroll
        for (int i = 0; i < 4; i++) {
            v[i] = xr[lane + 32*i];
            s += v[i].x + v[i].y + v[i].z + v[i].w;
        }
        #pragma unroll
        for (int o = 16; o; o >>= 1) s += __shfl_xor_sync(0xffffffff, s, o);
        float m = s * (1.0f/INC);
        float var = 0.0f;
        #pragma unroll
        for (int i = 0; i < 4; i++) {
            float dx=v[i].x-m, dy=v[i].y-m, dz=v[i].z-m, dw=v[i].w-m;
            var += dx*dx + dy*dy + dz*dz + dw*dw;
        }
        #pragma unroll
        for (int o = 16; o; o >>= 1) var += __shfl_xor_sync(0xffffffff, var, o);
        float inv = rsqrtf(var * (1.0f/INC) + 1e-5f);
        #pragma unroll
        for (int i = 0; i < 4; i++) {
            int c4 = lane + 32*i;
            float4 gg = ((const float4*)g1v)[c4];
            float4 ee = ((const float4*)be1)[c4];
            float4 o4;
            o4.x = gelu_exact((v[i].x - m)*inv*gg.x + ee.x);
            o4.y = gelu_exact((v[i].y - m)*inv*gg.y + ee.y);
            o4.z = gelu_exact((v[i].z - m)*inv*gg.z + ee.z);
            o4.w = gelu_exact((v[i].w - m)*inv*gg.w + ee.w);
            xr[c4] = o4;
        }
    }
    __syncthreads();

    // ---------------- Phase E: gemm2 + b2 (thread = col tid x 4 rows) ------
    unsigned long long acc[RPB];
    #pragma unroll
    for (int r = 0; r < RPB; r++) acc[r] = 0ull;
    {
        const float* wcol = w2 + tid;
        float wv[8], wn2[8];
        #pragma unroll
        for (int i = 0; i < 8; i++)
            wv[i] = __ldg(&wcol[(size_t)i*HID2]);
        #pragma unroll 1
        for (int k8 = 0; k8 < 512; k8 += 8) {
            if (k8 + 8 < 512) {
                #pragma unroll
                for (int i = 0; i < 8; i++)
                    wn2[i] = __ldg(&wcol[(size_t)(k8 + 8 + i)*HID2]);
            }
            #pragma unroll
            for (int kk = 0; kk < 8; kk += 4) {
                unsigned long long wd0 = pack2(wv[kk+0], wv[kk+1]);
                unsigned long long wd1 = pack2(wv[kk+2], wv[kk+3]);
                #pragma unroll
                for (int r = 0; r < RPB; r++) {
                    ulonglong2 ap = *(const ulonglong2*)&sA[r][k8 + kk];
                    fma2(acc[r], ap.x, wd0);
                    fma2(acc[r], ap.y, wd1);
                }
            }
            #pragma unroll
            for (int i = 0; i < 8; i++) wv[i] = wn2[i];
        }
    }
    float c[RPB];
    {
        float b2v = b2[tid];
        #pragma unroll
        for (int r = 0; r < RPB; r++) {
            float lo, hi;
            unpack2(lo, hi, acc[r]);
            c[r] = lo + hi + b2v;
        }
    }
    __syncthreads();   // all h1 reads done
    #pragma unroll
    for (int r = 0; r < RPB; r++) sA[r][tid] = c[r];
    __syncthreads();

    // ---------------- Phase F: LN2 + GELU + w3 + mask + coarse (warps 0-3) -
    if (warp < RPB) {
        float cc[8];
        {
            float4 cA = *(const float4*)&sA[warp][lane*8];
            float4 cB = *(const float4*)&sA[warp][lane*8 + 4];
            cc[0]=cA.x; cc[1]=cA.y; cc[2]=cA.z; cc[3]=cA.w;
            cc[4]=cB.x; cc[5]=cB.y; cc[6]=cB.z; cc[7]=cB.w;
        }
        float s2 = 0.0f;
        #pragma unroll
        for (int j = 0; j < 8; j++) s2 += cc[j];
        #pragma unroll
        for (int o = 16; o; o >>= 1) s2 += __shfl_xor_sync(0xffffffff, s2, o);
        float m2 = s2 * (1.0f/HID2);
        float v2 = 0.0f;
        #pragma unroll
        for (int j = 0; j < 8; j++) { float d = cc[j]-m2; v2 += d*d; }
        #pragma unroll
        for (int o = 16; o; o >>= 1) v2 += __shfl_xor_sync(0xffffffff, v2, o);
        float inv2 = rsqrtf(v2 * (1.0f/HID2) + 1e-5f);

        float h[8];
        {
            float4 gA = ((const float4*)g2v)[lane*2], gB = ((const float4*)g2v)[lane*2+1];
            float4 eA = ((const float4*)be2)[lane*2], eB = ((const float4*)be2)[lane*2+1];
            float gs[8] = {gA.x,gA.y,gA.z,gA.w,gB.x,gB.y,gB.z,gB.w};
            float es[8] = {eA.x,eA.y,eA.z,eA.w,eB.x,eB.y,eB.z,eB.w};
            #pragma unroll
            for (int j = 0; j < 8; j++)
                h[j] = gelu_exact((cc[j]-m2)*inv2*gs[j] + es[j]);
        }
        float a0 = 0.0f, a1 = 0.0f;
        #pragma unroll
        for (int j = 0; j < 4; j++) {
            float4 w = ((const float4*)w3)[lane*4 + j];
            a0 += h[2*j]*w.x + h[2*j+1]*w.z;
            a1 += h[2*j]*w.y + h[2*j+1]*w.w;
        }
        #pragma unroll
        for (int o = 16; o; o >>= 1) {
            a0 += __shfl_xor_sync(0xffffffff, a0, o);
            a1 += __shfl_xor_sync(0xffffffff, a1, o);
        }
        if (lane == 0) {
            int n = n0 + warp;
            float cv0 = scoarse[warp][0], cv1 = scoarse[warp][1];
            float m0 = mask[(size_t)(b*COUT + 0)*NPTS + n];
            float m1 = mask[(size_t)(b*COUT + 1)*NPTS + n];
            rend[(size_t)(b*COUT + 0)*NPTS + n] = (a0 + b3[0])*m0 + cv0;
            rend[(size_t)(b*COUT + 1)*NPTS + n] = (a1 + b3[1])*m1 + cv1;
        }
    }
}

// ---------------- launch: ONE kernel ----------------
extern "C" void kernel_launch(void* const* d_in, const int* in_sizes, int n_in,
                              void* d_out, int out_size)
{
    const float* res2       = (const float*)d_in[1];
    const float* out        = (const float*)d_in[2];
    const float* over_gen   = (const float*)d_in[3];
    const float* rand_point = (const float*)d_in[4];
    const float* mask       = (const float*)d_in[5];
    const float* w1  = (const float*)d_in[6];
    const float* b1  = (const float*)d_in[7];
    const float* g1  = (const float*)d_in[8];
    const float* be1 = (const float*)d_in[9];
    const float* w2  = (const float*)d_in[10];
    const float* b2  = (const float*)d_in[11];
    const float* g2  = (const float*)d_in[12];
    const float* be2 = (const float*)d_in[13];
    const float* w3  = (const float*)d_in[14];
    const float* b3  = (const float*)d_in[15];

    float* o_rend = (float*)d_out;                      // [8,2,128]
    float* o_pts  = o_rend + (size_t)BATCH*COUT*NPTS;   // [8,128,2]

    k_all<<<NROWS/RPB, 256>>>(out, res2, over_gen, rand_point, mask,
                              w1, b1, g1, be1, w2, b2, g2, be2, w3, b3,
                              o_rend, o_pts);
}